// round 16
// baseline (speedup 1.0000x reference)
#include <cuda_runtime.h>
#include <cuda_fp16.h>
#include <mma.h>
#include <math.h>
#include <stdint.h>

using namespace nvcuda;

#define NB 16
#define CCH 512
#define T0 6399
#define T1 1598
#define T2 798
#define T3 398
#define T4 198
#define T0P 6400
#define O1P 1664
#define O2P 896
#define O3P 512
#define O4P 256

#define PL_ELEMS  ((size_t)NB * 512 * T0P)
#define OUT_ELEMS ((size_t)NB * 512 * O1P)
#define F_ELEMS   ((size_t)NB * 512 * T4)
#define C_ELEMS   ((size_t)NB * 512 * 512)
#define OFF_PL   ((size_t)0)
#define OFF_OUT  (OFF_PL + PL_ELEMS / 2 + 1024)
#define OFF_FX   (OFF_OUT + OUT_ELEMS + 1024)
#define OFF_FY   (OFF_FX + F_ELEMS)
#define OFF_SX   (OFF_FY + F_ELEMS)
#define OFF_SY   (OFF_SX + NB * CCH)
#define POOL_TOTAL (OFF_SY + NB * CCH + 1024)
#define OFF_CXY  ((size_t)0)
#define OFF_CYX  (OFF_CXY + C_ELEMS)
#define OFF_CXX  (OFF_CYX + C_ELEMS)
#define OFF_CYY  (OFF_CXX + C_ELEMS)

__device__ float d_pool[POOL_TOTAL];
__device__ unsigned short d_WB[2 * 512 * 4096 + 6 * 512 * 2048];
__device__ double d_stats[2 * NB];
__device__ float d_w[3 * NB];
#define W1H ((size_t)0)
#define W1L (W1H + (size_t)512 * 4096)
#define W2H (W1L + (size_t)512 * 4096)
#define W2L (W2H + (size_t)512 * 2048)
#define W3H (W2L + (size_t)512 * 2048)
#define W3L (W3H + (size_t)512 * 2048)
#define W4H (W3L + (size_t)512 * 2048)
#define W4L (W4H + (size_t)512 * 2048)

// ---- cp.async helpers ----
__device__ __forceinline__ uint32_t smem_u32(const void* p) {
    uint32_t a;
    asm("{ .reg .u64 t; cvta.to.shared.u64 t, %1; cvt.u32.u64 %0, t; }" : "=r"(a) : "l"(p));
    return a;
}
__device__ __forceinline__ void cpa16(void* s, const void* g) {
    asm volatile("cp.async.cg.shared.global [%0], [%1], 16;" :: "r"(smem_u32(s)), "l"(g));
}
__device__ __forceinline__ void cpa8(void* s, const void* g) {
    asm volatile("cp.async.ca.shared.global [%0], [%1], 8;" :: "r"(smem_u32(s)), "l"(g));
}
__device__ __forceinline__ void cpa4(void* s, const void* g) {
    asm volatile("cp.async.ca.shared.global [%0], [%1], 4;" :: "r"(smem_u32(s)), "l"(g));
}
#define CP_COMMIT() asm volatile("cp.async.commit_group;" ::: "memory")
#define CP_WAIT1() asm volatile("cp.async.wait_group 1;" ::: "memory")
#define CP_WAIT0() asm volatile("cp.async.wait_group 0;" ::: "memory")

// ---- weight pack: fp16 hi/lo planes (W = Wh + Wl, exact to ~2^-22) ----
__global__ void packAll_k(const float* __restrict__ W1, const float* __restrict__ W2,
                          const float* __restrict__ W3, const float* __restrict__ W4,
                          unsigned short* __restrict__ wb) {
    const int S1 = 512 * 4096, S2 = 512 * 2048;
    int e = blockIdx.x * 256 + threadIdx.x;
    const float* src;
    size_t ho, lo_;
    int off;
    if (e < S1) { src = W1; off = e; ho = W1H; lo_ = W1L; }
    else {
        int r = e - S1;
        int seg = r / S2;
        off = r - seg * S2;
        if (seg == 0) { src = W2; ho = W2H; lo_ = W2L; }
        else if (seg == 1) { src = W3; ho = W3H; lo_ = W3L; }
        else { src = W4; ho = W4H; lo_ = W4L; }
    }
    float x = src[off];
    __half h = __float2half_rn(x);
    __half l = __float2half_rn(x - __half2float(h));
    wb[ho + off] = __half_as_ushort(h);
    wb[lo_ + off] = __half_as_ushort(l);
}

__device__ __forceinline__ float2 murs_of(const double* stats, int b, int L) {
    double mu = stats[2 * b] / L;
    double var = stats[2 * b + 1] / L - mu * mu;
    return make_float2((float)mu, (float)(1.0 / sqrt(var + 1e-5)));
}

// ---- conv0 (cin=1,k=10,s=5): stats + fused norm/pack (fp16 single plane) ----
__global__ void conv0_stats_k(const float* __restrict__ wav, const float* __restrict__ W0,
                              double* stats) {
    __shared__ float Ws[5120];
    __shared__ double r1[128], r2[128];
    int tid = threadIdx.x;
    for (int e = tid; e < 5120; e += 128) Ws[e] = W0[e];
    __syncthreads();
    int b = blockIdx.y, t = blockIdx.x * 128 + tid;
    double s = 0.0, q = 0.0;
    if (t < T0) {
        float w[10];
        const float* wp = wav + (size_t)b * 32000 + t * 5;
#pragma unroll
        for (int j = 0; j < 10; j++) w[j] = wp[j];
        for (int co = 0; co < 512; co++) {
            float a = 0.f;
#pragma unroll
            for (int j = 0; j < 10; j++) a = fmaf(Ws[co * 10 + j], w[j], a);
            s += a; q += (double)a * a;
        }
    }
    r1[tid] = s; r2[tid] = q;
    __syncthreads();
    for (int st = 64; st > 0; st >>= 1) {
        if (tid < st) { r1[tid] += r1[tid + st]; r2[tid] += r2[tid + st]; }
        __syncthreads();
    }
    if (tid == 0) { atomicAdd(&stats[2 * b], r1[0]); atomicAdd(&stats[2 * b + 1], r2[0]); }
}

__global__ void conv0_pack_k(const float* __restrict__ wav, const float* __restrict__ W0,
                             const float* __restrict__ g, const float* __restrict__ be,
                             const double* __restrict__ stats,
                             unsigned short* __restrict__ hip) {
    __shared__ float Ws[5120], gS[512], bS[512];
    int tid = threadIdx.x;
    for (int e = tid; e < 5120; e += 128) Ws[e] = W0[e];
    for (int e = tid; e < 512; e += 128) { gS[e] = g[e]; bS[e] = be[e]; }
    __syncthreads();
    int b = blockIdx.y, t = blockIdx.x * 128 + tid;
    if (t >= T0) return;
    float2 mr = murs_of(stats, b, 512 * T0);
    float w[10];
    const float* wp = wav + (size_t)b * 32000 + t * 5;
#pragma unroll
    for (int j = 0; j < 10; j++) w[j] = wp[j];
    size_t base = (size_t)b * 512 * T0P + t;
    for (int co = 0; co < 512; co++) {
        float a = 0.f;
#pragma unroll
        for (int j = 0; j < 10; j++) a = fmaf(Ws[co * 10 + j], w[j], a);
        float v = fmaxf((a - mr.x) * mr.y * gS[co] + bS[co], 0.f);
        hip[base + (size_t)co * T0P] = __half_as_ushort(__float2half_rn(v));
    }
}

// ---- WMMA conv GEMM: 128co x 128t, K-chunk 32, fp16 2-pass (Wh*B + Wl*B) ----
#define CHW 40
template <int KW, int SS>
__global__ __launch_bounds__(256) void conv_wmma(
    const unsigned short* __restrict__ hiP,
    const unsigned short* __restrict__ Whp, const unsigned short* __restrict__ Wlp,
    float* __restrict__ out, int TPin, int OUTP, int Tout, int K) {
    extern __shared__ char smem[];
    const int PLN = 128 * CHW;
    __half* bufs = (__half*)smem;  // 2 buffers x 3 planes (Ah, Al, Bh)
    int tid = threadIdx.x, wid = tid >> 5;
    int wc = wid & 3, wt = wid >> 2;
    int t0 = blockIdx.x * 128, co0 = blockIdx.y * 128, b = blockIdx.z;
    const unsigned short* hB = hiP + (size_t)b * 512 * TPin;

    wmma::fragment<wmma::accumulator, 16, 16, 16, float> c[2][4];
#pragma unroll
    for (int i = 0; i < 2; i++)
#pragma unroll
        for (int j = 0; j < 4; j++) wmma::fill_fragment(c[i][j], 0.0f);

    int KC = K >> 5;

    auto fill = [&](__half* bf, int ch) {
        int kb = ch << 5;
        __half* Ah = bf;
        __half* Al = bf + PLN;
        __half* Bh = bf + 2 * PLN;
        {   // A: hi+lo weight planes, 16B aligned
            int row = tid >> 1, half = tid & 1;
            const unsigned short* gh = Whp + (size_t)(co0 + row) * K + kb + half * 16;
            const unsigned short* gl = Wlp + (size_t)(co0 + row) * K + kb + half * 16;
            __half* dh = Ah + row * CHW + half * 16;
            __half* dl = Al + row * CHW + half * 16;
            cpa16(dh, gh); cpa16(dh + 8, gh + 8);
            cpa16(dl, gl); cpa16(dl + 8, gl + 8);
        }
        if (KW == 8) {  // B hi only: 8B-aligned global
#pragma unroll
            for (int r = 0; r < 2; r++) {
                int e = r * 256 + tid;
                int t = e & 127, cc = e >> 7;
                int tt = t0 + t; if (tt > Tout - 1) tt = Tout - 1;
                size_t s = (size_t)((kb >> 3) + cc) * TPin + (size_t)tt * SS;
                __half* dh = Bh + t * CHW + cc * 8;
                cpa8(dh, hB + s); cpa8(dh + 4, hB + s + 4);
            }
        } else {  // 4B-aligned global
#pragma unroll
            for (int r = 0; r < 4; r++) {
                int e = r * 256 + tid;
                int t = e & 127, cc = e >> 7;
                int tt = t0 + t; if (tt > Tout - 1) tt = Tout - 1;
                size_t s = (size_t)((kb >> 2) + cc) * TPin + (size_t)tt * SS;
                __half* dh = Bh + t * CHW + cc * 4;
                cpa4(dh, hB + s); cpa4(dh + 2, hB + s + 2);
            }
        }
    };

    fill(bufs, 0);
    CP_COMMIT();
    for (int ch = 0; ch < KC; ch++) {
        __half* cur = bufs + (ch & 1) * 3 * PLN;
        __half* nxt = bufs + ((ch + 1) & 1) * 3 * PLN;
        if (ch + 1 < KC) { fill(nxt, ch + 1); CP_COMMIT(); CP_WAIT1(); }
        else CP_WAIT0();
        __syncthreads();
        __half* Ah = cur;
        __half* Al = cur + PLN;
        __half* Bh = cur + 2 * PLN;
#pragma unroll
        for (int kk = 0; kk < 2; kk++) {
            wmma::fragment<wmma::matrix_a, 16, 16, 16, __half, wmma::row_major> ah[2], al[2];
#pragma unroll
            for (int i = 0; i < 2; i++) {
                wmma::load_matrix_sync(ah[i], Ah + (wc * 32 + i * 16) * CHW + kk * 16, CHW);
                wmma::load_matrix_sync(al[i], Al + (wc * 32 + i * 16) * CHW + kk * 16, CHW);
            }
#pragma unroll
            for (int j = 0; j < 4; j++) {
                wmma::fragment<wmma::matrix_b, 16, 16, 16, __half, wmma::col_major> bh;
                wmma::load_matrix_sync(bh, Bh + (wt * 64 + j * 16) * CHW + kk * 16, CHW);
#pragma unroll
                for (int i = 0; i < 2; i++) {
                    wmma::mma_sync(c[i][j], ah[i], bh, c[i][j]);
                    wmma::mma_sync(c[i][j], al[i], bh, c[i][j]);
                }
            }
        }
        __syncthreads();
    }
    float* ob = out + ((size_t)b * 512 + co0) * OUTP + t0;
#pragma unroll
    for (int i = 0; i < 2; i++)
#pragma unroll
        for (int j = 0; j < 4; j++)
            wmma::store_matrix_sync(ob + (size_t)(wc * 32 + i * 16) * OUTP + wt * 64 + j * 16,
                                    c[i][j], OUTP, wmma::mem_row_major);
}

// ---- stats / norm (stride-aware) ----
__global__ void zero_stats_k(double* stats) { if (threadIdx.x < 32) stats[threadIdx.x] = 0.0; }

__global__ void stats_k(const float* __restrict__ in, double* stats, int T, int TP) {
    __shared__ double s1[256], s2[256];
    int b = blockIdx.x;
    int L = 512 * T;
    int cs = (L + gridDim.y - 1) / gridDim.y;
    int start = blockIdx.y * cs, end = min(L, start + cs);
    const float* p = in + (size_t)b * 512 * TP;
    double s = 0.0, q = 0.0;
    for (int i = start + threadIdx.x; i < end; i += 256) {
        int c = i / T, t = i - c * T;
        double v = p[(size_t)c * TP + t];
        s += v; q += v * v;
    }
    s1[threadIdx.x] = s; s2[threadIdx.x] = q;
    __syncthreads();
    for (int st = 128; st > 0; st >>= 1) {
        if (threadIdx.x < st) { s1[threadIdx.x] += s1[threadIdx.x + st]; s2[threadIdx.x] += s2[threadIdx.x + st]; }
        __syncthreads();
    }
    if (threadIdx.x == 0) { atomicAdd(&stats[2 * b], s1[0]); atomicAdd(&stats[2 * b + 1], s2[0]); }
}

__global__ void normpack_k(const float* __restrict__ in, unsigned short* __restrict__ hip,
                           const float* __restrict__ g, const float* __restrict__ be,
                           const double* __restrict__ stats, int T, int TP) {
    long long total = (long long)NB * CCH * T;
    long long idx = (long long)blockIdx.x * 256 + threadIdx.x;
    if (idx >= total) return;
    int b = (int)(idx / ((long long)CCH * T));
    long long rem = idx - (long long)b * CCH * T;
    int c = (int)(rem / T), t = (int)(rem - (long long)c * T);
    float2 mr = murs_of(stats, b, 512 * T);
    size_t src = ((size_t)b * CCH + c) * TP + t;
    float v = fmaxf((in[src] - mr.x) * mr.y * g[c] + be[c], 0.f);
    hip[src] = __half_as_ushort(__float2half_rn(v));
}

__global__ void norm_k(const float* __restrict__ buf, float* __restrict__ outp,
                       const float* __restrict__ g, const float* __restrict__ be,
                       const double* __restrict__ stats, int T, int TP) {
    long long total = (long long)NB * CCH * T;
    long long idx = (long long)blockIdx.x * 256 + threadIdx.x;
    if (idx >= total) return;
    int b = (int)(idx / ((long long)CCH * T));
    long long rem = idx - (long long)b * CCH * T;
    int c = (int)(rem / T), t = (int)(rem - (long long)c * T);
    float2 mr = murs_of(stats, b, 512 * T);
    outp[idx] = fmaxf((buf[((size_t)b * CCH + c) * TP + t] - mr.x) * mr.y * g[c] + be[c], 0.f);
}

// ---- features -> cost -> sinkhorn ----
__global__ void sqnorm_k(const float* __restrict__ f, float* __restrict__ s) {
    int idx = blockIdx.x * 256 + threadIdx.x;
    if (idx >= NB * CCH) return;
    const float* p = f + (size_t)idx * T4;
    float acc = 0.f;
    for (int d = 0; d < T4; d++) acc = fmaf(p[d], p[d], acc);
    s[idx] = acc;
}

__global__ __launch_bounds__(256) void cost_k(const float* __restrict__ A, const float* __restrict__ Bf,
                                              const float* __restrict__ sa, const float* __restrict__ sb,
                                              float* __restrict__ Co) {
    __shared__ float As[64][17], Bs[64][17];
    int b = blockIdx.z;
    const float* Ab = A + (size_t)b * 512 * T4;
    const float* Bb = Bf + (size_t)b * 512 * T4;
    int n0 = blockIdx.y * 64, m0 = blockIdx.x * 64;
    int tid = threadIdx.x, rn = tid >> 4, cm = tid & 15;
    float acc[4][4];
#pragma unroll
    for (int i = 0; i < 4; i++)
#pragma unroll
        for (int j = 0; j < 4; j++) acc[i][j] = 0.f;
    for (int d0 = 0; d0 < T4; d0 += 16) {
#pragma unroll
        for (int q = 0; q < 4; q++) {
            int e = tid + q * 256, r = e >> 4, dd = e & 15;
            As[r][dd] = (d0 + dd < T4) ? Ab[(size_t)(n0 + r) * T4 + d0 + dd] : 0.f;
            Bs[r][dd] = (d0 + dd < T4) ? Bb[(size_t)(m0 + r) * T4 + d0 + dd] : 0.f;
        }
        __syncthreads();
#pragma unroll
        for (int dd = 0; dd < 16; dd++) {
            float a[4], bb[4];
#pragma unroll
            for (int i = 0; i < 4; i++) a[i] = As[rn * 4 + i][dd];
#pragma unroll
            for (int j = 0; j < 4; j++) bb[j] = Bs[cm * 4 + j][dd];
#pragma unroll
            for (int i = 0; i < 4; i++)
#pragma unroll
                for (int j = 0; j < 4; j++) acc[i][j] = fmaf(a[i], bb[j], acc[i][j]);
        }
        __syncthreads();
    }
    const float* sab = sa + b * 512;
    const float* sbb = sb + b * 512;
    float* Cb = Co + (size_t)b * 512 * 512;
#pragma unroll
    for (int i = 0; i < 4; i++) {
        int n = n0 + rn * 4 + i;
#pragma unroll
        for (int j = 0; j < 4; j++) {
            int m = m0 + cm * 4 + j;
            Cb[(size_t)n * 512 + m] = 0.5f * fmaxf(sab[n] + sbb[m] - 2.f * acc[i][j], 0.f);
        }
    }
}

__device__ __forceinline__ float lse_update(const float* cp, const float* pot) {
    const float IEPS = 400.f;
    float M = -3.4e38f, S = 0.f;
    for (int n = 0; n < 512; n += 8) {
        float v[8];
#pragma unroll
        for (int i = 0; i < 8; i++) v[i] = pot[n + i] - cp[(size_t)(n + i) << 9];
        float vm = v[0];
#pragma unroll
        for (int i = 1; i < 8; i++) vm = fmaxf(vm, v[i]);
        if (vm > M) {
            S *= __expf((M - vm) * IEPS);
            M = vm;
#pragma unroll
            for (int i = 0; i < 8; i++) S += __expf((v[i] - M) * IEPS);
        } else if (vm > M - 0.06f) {
#pragma unroll
            for (int i = 0; i < 8; i++) S += __expf((v[i] - M) * IEPS);
        }
    }
    const float LA = -6.2383246250395075f, EPS = 0.0025f;
    return -EPS * (LA + __logf(S)) - M;
}

__global__ __launch_bounds__(512) void sinkhorn_k(const float* __restrict__ Cxy, const float* __restrict__ Cyx,
                                                  const float* __restrict__ Cxx, const float* __restrict__ Cyy,
                                                  float* __restrict__ w) {
    __shared__ float fs[512], gs[512];
    int b = blockIdx.x, ot = blockIdx.y;
    size_t off = (size_t)b * 512 * 512;
    const float *Cg, *Cf;
    if (ot == 0) { Cg = Cxy + off; Cf = Cyx + off; }
    else if (ot == 1) { Cg = Cxx + off; Cf = Cg; }
    else { Cg = Cyy + off; Cf = Cg; }
    int tid = threadIdx.x;
    fs[tid] = 0.f; gs[tid] = 0.f;
    __syncthreads();
    for (int it = 0; it < 50; it++) {
        gs[tid] = lse_update(Cg + tid, fs);
        __syncthreads();
        fs[tid] = lse_update(Cf + tid, gs);
        __syncthreads();
    }
    fs[tid] += gs[tid];
    __syncthreads();
    for (int s = 256; s > 0; s >>= 1) {
        if (tid < s) fs[tid] += fs[tid + s];
        __syncthreads();
    }
    if (tid == 0) w[ot * 16 + b] = fs[0] * (1.f / 512.f);
}

__global__ void final_k(const float* __restrict__ w, float* __restrict__ out) {
    int b = threadIdx.x;
    if (b < NB) out[b] = w[b] - 0.5f * (w[16 + b] + w[32 + b]);
}

// ---- host driver ----
extern "C" void kernel_launch(void* const* d_in, const int* in_sizes, int n_in,
                              void* d_out, int out_size) {
    (void)out_size;
    const float* y_hat = (const float*)d_in[0];
    const float* y = (const float*)d_in[1];
    const float *W[5], *g[5], *be[5];
    if (n_in >= 17 && in_sizes[3] <= 1024) {
        for (int i = 0; i < 5; i++) {
            W[i] = (const float*)d_in[2 + 3 * i];
            g[i] = (const float*)d_in[3 + 3 * i];
            be[i] = (const float*)d_in[4 + 3 * i];
        }
    } else {
        for (int i = 0; i < 5; i++) {
            W[i] = (const float*)d_in[2 + i];
            g[i] = (const float*)d_in[7 + i];
            be[i] = (const float*)d_in[12 + i];
        }
    }
    float* out = (float*)d_out;

    float* pool; unsigned short* wb; double* stats; float* wv;
    cudaGetSymbolAddress((void**)&pool, d_pool);
    cudaGetSymbolAddress((void**)&wb, d_WB);
    cudaGetSymbolAddress((void**)&stats, d_stats);
    cudaGetSymbolAddress((void**)&wv, d_w);

    unsigned short* PL = (unsigned short*)(pool + OFF_PL);
    float* OUT = pool + OFF_OUT;
    float* fx = pool + OFF_FX;
    float* fy = pool + OFF_FY;
    float* sx = pool + OFF_SX;
    float* sy = pool + OFF_SY;

    const int SMEM_W = 2 * 3 * 128 * CHW * 2;  // 61440
    cudaFuncSetAttribute(conv_wmma<8, 4>, cudaFuncAttributeMaxDynamicSharedMemorySize, SMEM_W);
    cudaFuncSetAttribute(conv_wmma<4, 2>, cudaFuncAttributeMaxDynamicSharedMemorySize, SMEM_W);

    packAll_k<<<(512 * 4096 + 3 * 512 * 2048) / 256, 256>>>(W[1], W[2], W[3], W[4], wb);

    for (int s = 0; s < 2; s++) {
        const float* wav = s ? y : y_hat;
        float* feat = s ? fy : fx;

        unsigned short* h0 = PL;
        zero_stats_k<<<1, 32>>>(stats);
        conv0_stats_k<<<dim3((T0 + 127) / 128, NB), 128>>>(wav, W[0], stats);
        conv0_pack_k<<<dim3((T0 + 127) / 128, NB), 128>>>(wav, W[0], g[0], be[0], stats, h0);

        conv_wmma<8, 4><<<dim3(O1P / 128, 4, NB), 256, SMEM_W>>>(h0, wb + W1H, wb + W1L,
                                                                 OUT, T0P, O1P, T1, 4096);
        zero_stats_k<<<1, 32>>>(stats);
        stats_k<<<dim3(16, 48), 256>>>(OUT, stats, T1, O1P);
        unsigned short* h1 = PL;
        normpack_k<<<(unsigned)(((long long)NB * CCH * T1 + 255) / 256), 256>>>(OUT, h1, g[1], be[1], stats, T1, O1P);

        conv_wmma<4, 2><<<dim3(O2P / 128, 4, NB), 256, SMEM_W>>>(h1, wb + W2H, wb + W2L,
                                                                 OUT, O1P, O2P, T2, 2048);
        zero_stats_k<<<1, 32>>>(stats);
        stats_k<<<dim3(16, 48), 256>>>(OUT, stats, T2, O2P);
        unsigned short* h2 = PL;
        normpack_k<<<(unsigned)(((long long)NB * CCH * T2 + 255) / 256), 256>>>(OUT, h2, g[2], be[2], stats, T2, O2P);

        conv_wmma<4, 2><<<dim3(O3P / 128, 4, NB), 256, SMEM_W>>>(h2, wb + W3H, wb + W3L,
                                                                 OUT, O2P, O3P, T3, 2048);
        zero_stats_k<<<1, 32>>>(stats);
        stats_k<<<dim3(16, 48), 256>>>(OUT, stats, T3, O3P);
        unsigned short* h3 = PL;
        normpack_k<<<(unsigned)(((long long)NB * CCH * T3 + 255) / 256), 256>>>(OUT, h3, g[3], be[3], stats, T3, O3P);

        conv_wmma<4, 2><<<dim3(O4P / 128, 4, NB), 256, SMEM_W>>>(h3, wb + W4H, wb + W4L,
                                                                 OUT, O3P, O4P, T4, 2048);
        zero_stats_k<<<1, 32>>>(stats);
        stats_k<<<dim3(16, 48), 256>>>(OUT, stats, T4, O4P);
        norm_k<<<(unsigned)(((long long)NB * CCH * T4 + 255) / 256), 256>>>(OUT, feat, g[4], be[4], stats, T4, O4P);
    }

    sqnorm_k<<<(NB * CCH + 255) / 256, 256>>>(fx, sx);
    sqnorm_k<<<(NB * CCH + 255) / 256, 256>>>(fy, sy);

    float* Cxy = pool + OFF_CXY;
    float* Cyx = pool + OFF_CYX;
    float* Cxx = pool + OFF_CXX;
    float* Cyy = pool + OFF_CYY;
    cost_k<<<dim3(8, 8, NB), 256>>>(fx, fy, sx, sy, Cxy);
    cost_k<<<dim3(8, 8, NB), 256>>>(fy, fx, sy, sx, Cyx);
    cost_k<<<dim3(8, 8, NB), 256>>>(fx, fx, sx, sx, Cxx);
    cost_k<<<dim3(8, 8, NB), 256>>>(fy, fy, sy, sy, Cyy);

    sinkhorn_k<<<dim3(NB, 3), 512>>>(Cxy, Cyx, Cxx, Cyy, wv);
    final_k<<<1, 32>>>(wv, out);
}